// round 6
// baseline (speedup 1.0000x reference)
#include <cuda_runtime.h>
#include <cuda_bf16.h>

// GroupEmbedding: out[b,g,d] = sum_f x[b, group_idx[g,f]] * W[g,f,d] + bias[g,d]
// zeroed where masked_group_idx[b] == g.
// B=8192, NF=128, G=16, F=8, D=512. Pure HBM-write-bound (256 MB out).

#define B_TOTAL  8192
#define NF_      128
#define G_       16
#define F_       8
#define D_       512
#define D4_      (D_ / 4)      // 128 float4 per (b,g)
#define BROWS    64            // rows per block
#define NTHREADS 128           // one thread per d4 column

__global__ __launch_bounds__(NTHREADS)
void group_embedding_kernel(const float* __restrict__ x,
                            const float* __restrict__ W,
                            const float* __restrict__ bias,
                            const int*   __restrict__ gidx_raw,   // int32 view; may be int64 underneath
                            const int*   __restrict__ mgi_raw,    // int32 view; may be int64 underneath
                            float*       __restrict__ out)
{
    const int g  = blockIdx.x;          // 0..15
    const int b0 = blockIdx.y * BROWS;  // row tile base
    const int t  = threadIdx.x;         // 0..127 -> d4 column

    __shared__ float xs[BROWS][F_];
    __shared__ int   msk[BROWS];
    __shared__ int   cols[F_];
    __shared__ int   flags;             // bit0: gidx is int32; bit1: mgi is int32

    // --- dtype detection: int64 little-endian values (<128) have all-zero odd words ---
    if (t < 32) {
        int pg = gidx_raw[2 * t + 1];   // probes first 64 int32 words of each array
        int pm = mgi_raw[2 * t + 1];
        int gi32 = __any_sync(0xffffffffu, pg != 0);
        int mi32 = __any_sync(0xffffffffu, pm != 0);
        if (t == 0) flags = (gi32 ? 1 : 0) | (mi32 ? 2 : 0);
    }
    __syncthreads();
    const bool gidx_i32 = (flags & 1) != 0;
    const bool mgi_i32  = (flags & 2) != 0;

    if (t < F_) {
        int idx = g * F_ + t;
        cols[t] = gidx_i32 ? gidx_raw[idx] : gidx_raw[2 * idx];
    }
    __syncthreads();

    // --- W column (8 float4) and bias into registers; reused for 64 rows ---
    const float4* __restrict__ W4 = (const float4*)W;
    float4 w[F_];
#pragma unroll
    for (int f = 0; f < F_; f++)
        w[f] = W4[(g * F_ + f) * D4_ + t];
    const float4 bb = ((const float4*)bias)[g * D4_ + t];

    // --- gather x tile + masks into shared ---
    for (int i = t; i < BROWS * F_; i += NTHREADS) {
        int r = i >> 3, f = i & 7;
        xs[r][f] = x[(b0 + r) * NF_ + cols[f]];
    }
    for (int i = t; i < BROWS; i += NTHREADS) {
        int b = b0 + i;
        msk[i] = mgi_i32 ? mgi_raw[b] : mgi_raw[2 * b];
    }
    __syncthreads();

    // --- mainloop: 32 FFMA + 1 coalesced STG.128 per row ---
    float4* __restrict__ out4 = (float4*)out;
#pragma unroll 4
    for (int r = 0; r < BROWS; r++) {
        float4 acc = bb;
#pragma unroll
        for (int f = 0; f < F_; f++) {
            const float xv = xs[r][f];
            acc.x = fmaf(xv, w[f].x, acc.x);
            acc.y = fmaf(xv, w[f].y, acc.y);
            acc.z = fmaf(xv, w[f].z, acc.z);
            acc.w = fmaf(xv, w[f].w, acc.w);
        }
        if (msk[r] == g) acc = make_float4(0.f, 0.f, 0.f, 0.f);
        out4[((size_t)(b0 + r) * G_ + g) * D4_ + t] = acc;
    }
}

extern "C" void kernel_launch(void* const* d_in, const int* in_sizes, int n_in,
                              void* d_out, int out_size)
{
    const float* x    = (const float*)d_in[0];
    const float* W    = (const float*)d_in[1];
    const float* bias = (const float*)d_in[2];
    const int*   gidx = (const int*)d_in[3];   // int32 or int64, detected in-kernel
    const int*   mgi  = (const int*)d_in[4];
    float*       out  = (float*)d_out;

    dim3 grid(G_, B_TOTAL / BROWS);   // 16 x 128 = 2048 blocks
    group_embedding_kernel<<<grid, NTHREADS>>>(x, W, bias, gidx, mgi, out);
}